// round 3
// baseline (speedup 1.0000x reference)
#include <cuda_runtime.h>

// CapsuleConvTranspose2d (2,64,32,32) -> (2,64,64,64), stride2 3x3, 8/8 caps,
// 3-iter k-means routing + squash + bias.
//
// Transposed-conv structure: patch[n,c,kh,kw,p,q] = x[n,c,(p+kh-1)/2,(q+kw-1)/2]
// iff (p+kh-1) even & in [0,62]; else 0. Valid kh set depends only on parity of p
// (even -> {1}, odd -> {0,2}); the p=63 border makes tap kh=2 out-of-range, which
// we handle by zero-filling (a zero prior routes identically to an absent one:
// exp(-lmax) in Z, nothing in the sums; nzeros = 72 - 8*ntap already counts the
// rest). Same for q/kw.
//
// 64 threads per pixel: g = tid>>3 (out capsule), r = tid&7. Lane r owns priors
// i = r + 8k, all sharing tap t = r % ntap; priors live in registers, routing is
// register + shuffle only. Weights are staged in smem [t][l][g][m] and read as
// float4.

template<int NKH, int NKW>
__device__ __forceinline__ void caps_pixel(
    int n, int p, int q,
    const float* __restrict__ x, const float* __restrict__ wt,
    const float* __restrict__ bs, float* __restrict__ y,
    float* __restrict__ s_w, float (*__restrict__ s_x)[64])
{
    constexpr int NTAP  = NKH * NKW;      // 1, 2, 4
    constexpr int CNT   = NTAP;           // priors per lane
    constexpr int FSTEP = 8 / NTAP;
    constexpr int NV    = 8 * NTAP;
    constexpr float NZEROS = (float)(72 - NV);
    constexpr int WPITCH = 528;           // 512 + 16 pad (bank de-cluster)

    const int tid = threadIdx.x;
    const int g = tid >> 3;
    const int r = tid & 7;

    int khs[2], kws[2];
    khs[0] = (NKH == 1) ? 1 : 0;  khs[1] = 2;
    kws[0] = (NKW == 1) ? 1 : 0;  kws[1] = 2;

    // ---- stage x: NTAP positions x 64 channels (zero-fill OOB border taps) ----
    #pragma unroll
    for (int pos = 0; pos < NTAP; pos++) {
        int a = pos / NKW, b = pos % NKW;
        int i = (p + khs[a] - 1) >> 1;          // >= 0 by construction
        int j = (q + kws[b] - 1) >> 1;
        bool valid = (i < 32) && (j < 32);      // only kh/kw==2 at p/q==63 fails
        s_x[pos][tid] = valid ? x[((n * 64 + tid) * 32 + i) * 32 + j] : 0.f;
    }

    // ---- stage weights: s_w[t][l][g][m], 512 floats per tap ----
    #pragma unroll
    for (int t = 0; t < NTAP; t++) {
        int a = t / NKW, b = t % NKW;
        int woff = (2 - khs[a]) * 3 + (2 - kws[b]);   // flipped kernel tap
        #pragma unroll
        for (int u = 0; u < 8; u++) {
            int e = u * 64 + tid;                     // e = (l*8+g)*8+m
            s_w[t * WPITCH + e] = wt[e * 9 + woff];
        }
    }
    __syncthreads();

    // ---- compute owned priors fully in registers ----
    const int tp = (NTAP == 1) ? 0 : (r % NTAP);
    const int f0 = (NTAP == 1) ? r : (r / NTAP);
    const float* wrow = s_w + tp * WPITCH + g * 8;

    float pri[CNT][8];
    #pragma unroll
    for (int k = 0; k < CNT; k++)
        #pragma unroll
        for (int m = 0; m < 8; m++) pri[k][m] = 0.f;

    #pragma unroll
    for (int l = 0; l < 8; l++) {
        float4 w0 = *(const float4*)(wrow + l * 64);
        float4 w1 = *(const float4*)(wrow + l * 64 + 4);
        #pragma unroll
        for (int k = 0; k < CNT; k++) {
            float xv = s_x[tp][(f0 + k * FSTEP) * 8 + l];
            pri[k][0] = fmaf(xv, w0.x, pri[k][0]);
            pri[k][1] = fmaf(xv, w0.y, pri[k][1]);
            pri[k][2] = fmaf(xv, w0.z, pri[k][2]);
            pri[k][3] = fmaf(xv, w0.w, pri[k][3]);
            pri[k][4] = fmaf(xv, w1.x, pri[k][4]);
            pri[k][5] = fmaf(xv, w1.y, pri[k][5]);
            pri[k][6] = fmaf(xv, w1.z, pri[k][6]);
            pri[k][7] = fmaf(xv, w1.w, pri[k][7]);
        }
    }

    const unsigned FULL = 0xffffffffu;

    // ---- routing init: mean over all 72 (zeros included in divisor) ----
    float o[8];
    #pragma unroll
    for (int m = 0; m < 8; m++) {
        float s = pri[0][m];
        #pragma unroll
        for (int k = 1; k < CNT; k++) s += pri[k][m];
        o[m] = s;
    }
    #pragma unroll
    for (int d = 1; d < 8; d <<= 1)
        #pragma unroll
        for (int m = 0; m < 8; m++)
            o[m] += __shfl_xor_sync(FULL, o[m], d, 8);
    #pragma unroll
    for (int m = 0; m < 8; m++) o[m] *= (1.0f / 72.0f);

    #pragma unroll
    for (int it = 0; it < 3; it++) {
        float sn = 0.f;
        #pragma unroll
        for (int m = 0; m < 8; m++) sn = fmaf(o[m], o[m], sn);
        float inv = 1.0f / fmaxf(sqrtf(sn), 1e-12f);

        float lg[CNT];
        float lmax = 0.0f;                      // zero-priors pin lmax >= 0
        #pragma unroll
        for (int k = 0; k < CNT; k++) {
            float s = 0.f;
            #pragma unroll
            for (int m = 0; m < 8; m++) s = fmaf(pri[k][m], o[m], s);
            s *= inv;
            lg[k] = s;
            lmax = fmaxf(lmax, s);
        }
        lmax = fmaxf(lmax, __shfl_xor_sync(FULL, lmax, 1, 8));
        lmax = fmaxf(lmax, __shfl_xor_sync(FULL, lmax, 2, 8));
        lmax = fmaxf(lmax, __shfl_xor_sync(FULL, lmax, 4, 8));

        float e[CNT];
        float z = 0.f;
        #pragma unroll
        for (int k = 0; k < CNT; k++) {
            e[k] = __expf(lg[k] - lmax);
            z += e[k];
        }
        z += __shfl_xor_sync(FULL, z, 1, 8);
        z += __shfl_xor_sync(FULL, z, 2, 8);
        z += __shfl_xor_sync(FULL, z, 4, 8);
        z += NZEROS * __expf(-lmax);            // zero-priors' Z share

        float acc[8];
        #pragma unroll
        for (int m = 0; m < 8; m++) acc[m] = e[0] * pri[0][m];
        #pragma unroll
        for (int k = 1; k < CNT; k++)
            #pragma unroll
            for (int m = 0; m < 8; m++)
                acc[m] = fmaf(e[k], pri[k][m], acc[m]);
        #pragma unroll
        for (int d = 1; d < 8; d <<= 1)
            #pragma unroll
            for (int m = 0; m < 8; m++)
                acc[m] += __shfl_xor_sync(FULL, acc[m], d, 8);

        float rz = 1.0f / z;
        #pragma unroll
        for (int m = 0; m < 8; m++) o[m] = acc[m] * rz;
    }

    // ---- squash + bias; lane r writes channel g*8+r ----
    float sn = 0.f;
    #pragma unroll
    for (int m = 0; m < 8; m++) sn = fmaf(o[m], o[m], sn);
    float scale = sn / ((1.0f + sn) * sqrtf(sn + 1e-12f));
    float val = o[r] * scale + bs[g * 8 + r];

    y[((n * 64 + g * 8 + r) * 64 + p) * 64 + q] = val;
}

__global__ __launch_bounds__(64)
void caps_kernel(const float* __restrict__ x,
                 const float* __restrict__ wt,
                 const float* __restrict__ bs,
                 float* __restrict__ y)
{
    __shared__ float s_w[4 * 528];
    __shared__ float s_x[4][64];

    const int pix = blockIdx.x;
    const int q = pix & 63;
    const int p = (pix >> 6) & 63;
    const int n = pix >> 12;

    const bool po = (p & 1) != 0;   // odd p -> kh in {0,2}
    const bool qo = (q & 1) != 0;

    if (!po) {
        if (!qo) caps_pixel<1, 1>(n, p, q, x, wt, bs, y, s_w, s_x);
        else     caps_pixel<1, 2>(n, p, q, x, wt, bs, y, s_w, s_x);
    } else {
        if (!qo) caps_pixel<2, 1>(n, p, q, x, wt, bs, y, s_w, s_x);
        else     caps_pixel<2, 2>(n, p, q, x, wt, bs, y, s_w, s_x);
    }
}

extern "C" void kernel_launch(void* const* d_in, const int* in_sizes, int n_in,
                              void* d_out, int out_size) {
    const float* x  = (const float*)d_in[0];
    const float* wt = (const float*)d_in[1];
    const float* bs = (const float*)d_in[2];
    float* y = (float*)d_out;
    caps_kernel<<<2 * 64 * 64, 64>>>(x, wt, bs, y);
}